// round 2
// baseline (speedup 1.0000x reference)
#include <cuda_runtime.h>
#include <cstdint>

#define TT 512
#define NB 128
#define EE 200
#define H4G 800
#define NSAMP 32768
#define RCTAS 100
#define KC 20

// ---------------- static scratch (no allocation) ----------------
__device__ float g_x[(size_t)TT * EE * NB];        // (t, e, b)
__device__ float g_pre_f[(size_t)TT * H4G * NB];   // (t, gate, b)
__device__ float g_pre_b[(size_t)TT * H4G * NB];
__device__ float g_h0[(size_t)TT * 400 * NB];      // layer0 out (t, u, b)
__device__ float g_hbt[(size_t)NB * TT * 400];     // layer1 out (b, t, u)
__device__ float g_hid[(size_t)NSAMP * 200];       // MLP hidden (s, n)
__device__ float g_hbuf0[2 * 200 * NB];            // h ping-pong [dir][u][b]
__device__ float g_hbuf1[2 * 200 * NB];
__device__ unsigned g_barCnt;
__device__ unsigned g_barGen;

__device__ __forceinline__ float sigf(float x) { return 1.f / (1.f + expf(-x)); }

// Sense-reversal grid barrier; requires all RCTAS CTAs co-resident.
__device__ __forceinline__ void grid_barrier() {
    __threadfence();
    __syncthreads();
    if (threadIdx.x == 0) {
        unsigned gen = atomicAdd(&g_barGen, 0u);
        unsigned a = atomicAdd(&g_barCnt, 1u);
        if (a == RCTAS - 1u) {
            atomicExch(&g_barCnt, 0u);
            __threadfence();
            atomicAdd(&g_barGen, 1u);
        } else {
            volatile unsigned* vg = &g_barGen;
            while (*vg == gen) { __nanosleep(64); }
        }
        __threadfence();
    }
    __syncthreads();
}

// ---------------- embedding: g_x[t][e][b] = emb[tokens[t][b]][e] ----------------
__global__ void k_embed(const int* __restrict__ tokens, const float* __restrict__ emb) {
    int t = blockIdx.x;
    __shared__ int stok[NB];
    if (threadIdx.x < NB) stok[threadIdx.x] = tokens[t * NB + threadIdx.x];
    __syncthreads();
    float* xo = g_x + (size_t)t * EE * NB;
    for (int lin = threadIdx.x; lin < EE * NB; lin += blockDim.x) {
        int e = lin >> 7, b = lin & 127;
        xo[lin] = __ldg(&emb[(size_t)stok[b] * EE + e]);
    }
}

// ---------------- pre GEMM: C[t][m][b] = sum_k W[m][k] * X[t][k][b] + bias1[m]+bias2[m]
// grid (ceil(M/64), TT), 256 threads, tile 64x128, BK=8, micro 4x8
__global__ __launch_bounds__(256) void k_gemm_wx(
    const float* __restrict__ W,
    const float* __restrict__ bias1, const float* __restrict__ bias2,
    int xsel, int csel, int M, int K)
{
    const float* X = xsel ? g_h0 : g_x;
    float* C = csel ? g_pre_b : g_pre_f;
    __shared__ float As[8][64];
    __shared__ float Bs[8][128];
    const int tid = threadIdx.x;
    const int m0 = blockIdx.x * 64;
    const float* Xb = X + (size_t)blockIdx.y * K * NB;
    float* Cb = C + (size_t)blockIdx.y * M * NB;
    const int la_m = tid >> 2;
    const int la_k = (tid & 3) * 2;
    const int lb_k = tid >> 5;
    const int lb_b = (tid & 31) * 4;
    const int tm = (tid >> 4) * 4;
    const int tn = (tid & 15) * 8;
    float acc[4][8];
#pragma unroll
    for (int i = 0; i < 4; i++)
#pragma unroll
        for (int j = 0; j < 8; j++) acc[i][j] = 0.f;

    for (int k0 = 0; k0 < K; k0 += 8) {
        float2 av = make_float2(0.f, 0.f);
        if (m0 + la_m < M)
            av = *(const float2*)&W[(size_t)(m0 + la_m) * K + k0 + la_k];
        float4 bv = *(const float4*)&Xb[(size_t)(k0 + lb_k) * NB + lb_b];
        __syncthreads();
        As[la_k][la_m] = av.x;
        As[la_k + 1][la_m] = av.y;
        *(float4*)&Bs[lb_k][lb_b] = bv;
        __syncthreads();
#pragma unroll
        for (int kk = 0; kk < 8; kk++) {
            float4 a = *(float4*)&As[kk][tm];
            float4 b0 = *(float4*)&Bs[kk][tn];
            float4 b1 = *(float4*)&Bs[kk][tn + 4];
            float avv[4] = {a.x, a.y, a.z, a.w};
            float bvv[8] = {b0.x, b0.y, b0.z, b0.w, b1.x, b1.y, b1.z, b1.w};
#pragma unroll
            for (int i = 0; i < 4; i++)
#pragma unroll
                for (int j = 0; j < 8; j++) acc[i][j] += avv[i] * bvv[j];
        }
    }
#pragma unroll
    for (int r = 0; r < 4; r++) {
        int m = m0 + tm + r;
        if (m < M) {
            float bs = __ldg(&bias1[m]) + __ldg(&bias2[m]);
            float4 o0 = make_float4(acc[r][0] + bs, acc[r][1] + bs, acc[r][2] + bs, acc[r][3] + bs);
            float4 o1 = make_float4(acc[r][4] + bs, acc[r][5] + bs, acc[r][6] + bs, acc[r][7] + bs);
            *(float4*)&Cb[(size_t)m * NB + tn] = o0;
            *(float4*)&Cb[(size_t)m * NB + tn + 4] = o1;
        }
    }
}

// ---------------- persistent BiLSTM layer: 100 CTAs (50/dir, 4 units each), 128 thr
__global__ __launch_bounds__(128) void k_recur(
    const float* __restrict__ whh_f, const float* __restrict__ whh_b, int layer)
{
    __shared__ float Wt[200][16];          // [k][r], r = gate*4 + u
    __shared__ float Hs[2][KC][NB];
    __shared__ float Cs[4][NB];
    __shared__ float Gs[16][NB];

    const int tid = threadIdx.x;
    const int dir = blockIdx.x / 50;
    const int ub = (blockIdx.x % 50) * 4;
    const float* whh = dir ? whh_b : whh_f;
    const float* pre = dir ? g_pre_b : g_pre_f;
    float* hb0 = g_hbuf0 + dir * 200 * NB;
    float* hb1 = g_hbuf1 + dir * 200 * NB;

    for (int idx = tid; idx < 3200; idx += 128) {
        int r = idx & 15, k = idx >> 4;
        int grow = (r >> 2) * 200 + ub + (r & 3);
        Wt[k][r] = whh[(size_t)grow * 200 + k];
    }
    {
        int b = tid;
#pragma unroll
        for (int u = 0; u < 4; u++) {
            Cs[u][b] = 0.f;
            hb0[(ub + u) * NB + b] = 0.f;
        }
    }
    grid_barrier();

    const int ry = tid >> 5;       // 0..3 -> rows ry*4..+3
    const int bx = (tid & 31) * 4; // cols bx..+3

    for (int s = 0; s < TT; s++) {
        const int t = dir ? (TT - 1 - s) : s;
        const float* hprev = (s & 1) ? hb1 : hb0;
        float* hnext = (s & 1) ? hb0 : hb1;
        const float* pt = pre + (size_t)t * H4G * NB;

        // issue pre loads early (consumed at the end)
        float4 pv[4];
#pragma unroll
        for (int r = 0; r < 4; r++) {
            int rr = ry * 4 + r;
            int grow = (rr >> 2) * 200 + ub + (rr & 3);
            pv[r] = *(const float4*)&pt[(size_t)grow * NB + bx];
        }

        float acc[4][4];
#pragma unroll
        for (int i = 0; i < 4; i++)
#pragma unroll
            for (int j = 0; j < 4; j++) acc[i][j] = 0.f;

        // stage chunk 0 (h read via L2 - L1 is stale across grid barrier)
        float4 pr[5];
#pragma unroll
        for (int i = 0; i < 5; i++) {
            int idx = tid + i * 128;
            pr[i] = __ldcg((const float4*)&hprev[(idx >> 5) * NB + (idx & 31) * 4]);
        }
#pragma unroll
        for (int i = 0; i < 5; i++) {
            int idx = tid + i * 128;
            *(float4*)&Hs[0][idx >> 5][(idx & 31) * 4] = pr[i];
        }
        __syncthreads();

        for (int kc = 0; kc < 10; kc++) {
            const int cur = kc & 1;
            if (kc < 9) {
#pragma unroll
                for (int i = 0; i < 5; i++) {
                    int idx = tid + i * 128;
                    pr[i] = __ldcg((const float4*)&hprev[((kc + 1) * KC + (idx >> 5)) * NB + (idx & 31) * 4]);
                }
            }
#pragma unroll 5
            for (int kk = 0; kk < KC; kk++) {
                float4 w = *(float4*)&Wt[kc * KC + kk][ry * 4];
                float4 h = *(float4*)&Hs[cur][kk][bx];
                acc[0][0] += w.x * h.x; acc[0][1] += w.x * h.y; acc[0][2] += w.x * h.z; acc[0][3] += w.x * h.w;
                acc[1][0] += w.y * h.x; acc[1][1] += w.y * h.y; acc[1][2] += w.y * h.z; acc[1][3] += w.y * h.w;
                acc[2][0] += w.z * h.x; acc[2][1] += w.z * h.y; acc[2][2] += w.z * h.z; acc[2][3] += w.z * h.w;
                acc[3][0] += w.w * h.x; acc[3][1] += w.w * h.y; acc[3][2] += w.w * h.z; acc[3][3] += w.w * h.w;
            }
            if (kc < 9) {
#pragma unroll
                for (int i = 0; i < 5; i++) {
                    int idx = tid + i * 128;
                    *(float4*)&Hs[cur ^ 1][idx >> 5][(idx & 31) * 4] = pr[i];
                }
            }
            __syncthreads();
        }

        // add pre, stage gate values
#pragma unroll
        for (int r = 0; r < 4; r++) {
            float4 o;
            o.x = acc[r][0] + pv[r].x;
            o.y = acc[r][1] + pv[r].y;
            o.z = acc[r][2] + pv[r].z;
            o.w = acc[r][3] + pv[r].w;
            *(float4*)&Gs[ry * 4 + r][bx] = o;
        }
        __syncthreads();

        // gate phase: 4 units x 128 batch, 4 items/thread
#pragma unroll
        for (int it = 0; it < 4; it++) {
            int item = tid + it * 128;
            int u = item >> 7, b = item & 127;
            float vi = Gs[u][b], vf = Gs[4 + u][b], vg = Gs[8 + u][b], vo = Gs[12 + u][b];
            float c = sigf(vf) * Cs[u][b] + sigf(vi) * tanhf(vg);
            float h = sigf(vo) * tanhf(c);
            Cs[u][b] = c;
            hnext[(ub + u) * NB + b] = h;
            if (layer == 0)
                g_h0[((size_t)t * 400 + dir * 200 + ub + u) * NB + b] = h;
            else
                g_hbt[((size_t)b * TT + t) * 400 + dir * 200 + ub + u] = h;
        }
        grid_barrier();
    }
}

// ---------------- fused path-gather + MLP1 (tanh): tile 64 samples x 64 units, K=800
__global__ __launch_bounds__(256) void k_gather_mlp1(
    const int* __restrict__ paths, const float* __restrict__ w1, const float* __restrict__ b1)
{
    __shared__ float As[8][64];
    __shared__ float Bs[8][64];
    __shared__ long long abase[64][2];
    const int tid = threadIdx.x;
    const int s0 = blockIdx.x * 64;
    const int n0 = blockIdx.y * 64;

    if (tid < 128) {
        int i = tid >> 1, j = tid & 1;
        int s = s0 + i;
        int tval = paths[(size_t)s * 2 + j];
        int b = s >> 8;
        abase[i][j] = (tval >= 0) ? ((long long)b * TT + tval) * 400LL : -1LL;
    }
    __syncthreads();

    const int la_i = tid >> 2;
    const int la_k = (tid & 3) * 2;
    const int tm = (tid >> 4) * 4;
    const int tn = (tid & 15) * 4;
    float acc[4][4];
#pragma unroll
    for (int i = 0; i < 4; i++)
#pragma unroll
        for (int j = 0; j < 4; j++) acc[i][j] = 0.f;

    for (int k0 = 0; k0 < 800; k0 += 8) {
        int k = k0 + la_k;
        int j = (k >= 400) ? 1 : 0;
        int u = k - j * 400;
        long long base = abase[la_i][j];
        float2 av = make_float2(0.f, 0.f);
        if (base >= 0) av = *(const float2*)&g_hbt[base + u];
        float2 bv = make_float2(0.f, 0.f);
        int n = n0 + la_i;
        if (n < 200) bv = *(const float2*)&w1[(size_t)n * 800 + k0 + la_k];
        __syncthreads();
        As[la_k][la_i] = av.x;
        As[la_k + 1][la_i] = av.y;
        Bs[la_k][la_i] = bv.x;
        Bs[la_k + 1][la_i] = bv.y;
        __syncthreads();
#pragma unroll
        for (int kk = 0; kk < 8; kk++) {
            float4 a = *(float4*)&As[kk][tm];
            float4 b4 = *(float4*)&Bs[kk][tn];
            float avv[4] = {a.x, a.y, a.z, a.w};
            float bvv[4] = {b4.x, b4.y, b4.z, b4.w};
#pragma unroll
            for (int i = 0; i < 4; i++)
#pragma unroll
                for (int j2 = 0; j2 < 4; j2++) acc[i][j2] += avv[i] * bvv[j2];
        }
    }
#pragma unroll
    for (int r = 0; r < 4; r++) {
        int s = s0 + tm + r;
#pragma unroll
        for (int c = 0; c < 4; c++) {
            int n = n0 + tn + c;
            if (n < 200)
                g_hid[(size_t)s * 200 + n] = tanhf(acc[r][c] + __ldg(&b1[n]));
        }
    }
}

// ---------------- MLP2 + softmax: one warp per sample ----------------
__global__ __launch_bounds__(128) void k_mlp2(
    const float* __restrict__ w2, const float* __restrict__ b2, float* __restrict__ out)
{
    __shared__ float w2s[800];
    __shared__ float b2s[4];
    const int tid = threadIdx.x;
    for (int i = tid; i < 800; i += 128) w2s[i] = w2[i];
    if (tid < 4) b2s[tid] = b2[tid];
    __syncthreads();
    const int warp = tid >> 5, lane = tid & 31;
    const int s = blockIdx.x * 4 + warp;
    const float* hr = g_hid + (size_t)s * 200;
    float a0 = 0.f, a1 = 0.f, a2 = 0.f, a3 = 0.f;
    for (int k = lane; k < 200; k += 32) {
        float h = hr[k];
        a0 += h * w2s[k];
        a1 += h * w2s[200 + k];
        a2 += h * w2s[400 + k];
        a3 += h * w2s[600 + k];
    }
#pragma unroll
    for (int o = 16; o > 0; o >>= 1) {
        a0 += __shfl_down_sync(0xffffffffu, a0, o);
        a1 += __shfl_down_sync(0xffffffffu, a1, o);
        a2 += __shfl_down_sync(0xffffffffu, a2, o);
        a3 += __shfl_down_sync(0xffffffffu, a3, o);
    }
    if (lane == 0) {
        float l0 = a0 + b2s[0], l1 = a1 + b2s[1], l2 = a2 + b2s[2], l3 = a3 + b2s[3];
        float m = fmaxf(fmaxf(l0, l1), fmaxf(l2, l3));
        float e0 = expf(l0 - m), e1 = expf(l1 - m), e2 = expf(l2 - m), e3 = expf(l3 - m);
        float inv = 1.f / (e0 + e1 + e2 + e3);
        float4 r = make_float4(e0 * inv, e1 * inv, e2 * inv, e3 * inv);
        *(float4*)&out[(size_t)s * 4] = r;
    }
}

extern "C" void kernel_launch(void* const* d_in, const int* in_sizes, int n_in,
                              void* d_out, int out_size)
{
    const int* tokens = (const int*)d_in[0];
    const int* paths = (const int*)d_in[1];
    const float* emb = (const float*)d_in[2];
    const float* wih0f = (const float*)d_in[3];
    const float* whh0f = (const float*)d_in[4];
    const float* bih0f = (const float*)d_in[5];
    const float* bhh0f = (const float*)d_in[6];
    const float* wih0b = (const float*)d_in[7];
    const float* whh0b = (const float*)d_in[8];
    const float* bih0b = (const float*)d_in[9];
    const float* bhh0b = (const float*)d_in[10];
    const float* wih1f = (const float*)d_in[11];
    const float* whh1f = (const float*)d_in[12];
    const float* bih1f = (const float*)d_in[13];
    const float* bhh1f = (const float*)d_in[14];
    const float* wih1b = (const float*)d_in[15];
    const float* whh1b = (const float*)d_in[16];
    const float* bih1b = (const float*)d_in[17];
    const float* bhh1b = (const float*)d_in[18];
    const float* w1 = (const float*)d_in[19];
    const float* b1 = (const float*)d_in[20];
    const float* w2 = (const float*)d_in[21];
    const float* b2 = (const float*)d_in[22];
    float* out = (float*)d_out;

    k_embed<<<TT, 256>>>(tokens, emb);

    dim3 gp(13, TT);
    k_gemm_wx<<<gp, 256>>>(wih0f, bih0f, bhh0f, 0, 0, 800, 200);
    k_gemm_wx<<<gp, 256>>>(wih0b, bih0b, bhh0b, 0, 1, 800, 200);
    k_recur<<<RCTAS, 128>>>(whh0f, whh0b, 0);

    k_gemm_wx<<<gp, 256>>>(wih1f, bih1f, bhh1f, 1, 0, 800, 400);
    k_gemm_wx<<<gp, 256>>>(wih1b, bih1b, bhh1b, 1, 1, 800, 400);
    k_recur<<<RCTAS, 128>>>(whh1f, whh1b, 1);

    dim3 g4(NSAMP / 64, 4);
    k_gather_mlp1<<<g4, 256>>>(paths, w1, b1);
    k_mlp2<<<NSAMP / 4, 128>>>(w2, b2, out);
}

// round 3
// speedup vs baseline: 1.0312x; 1.0312x over previous
#include <cuda_runtime.h>
#include <cstdint>

#define TT 512
#define NB 128
#define EE 200
#define H4G 800
#define NSAMP 32768
#define RCTAS 100
#define KC 20

// ---------------- static scratch (no allocation) ----------------
__device__ float g_x[(size_t)TT * EE * NB];        // (t, e, b)
__device__ float g_pre_f[(size_t)TT * H4G * NB];   // (t, gate, b)
__device__ float g_pre_b[(size_t)TT * H4G * NB];
__device__ float g_h0[(size_t)TT * 400 * NB];      // layer0 out (t, u, b)
__device__ float g_hbt[(size_t)NB * TT * 400];     // layer1 out (b, t, u)
__device__ float g_hid[(size_t)NSAMP * 200];       // MLP hidden (s, n)
__device__ float g_hbuf0[2 * 200 * NB];            // h ping-pong [dir][u][b]
__device__ float g_hbuf1[2 * 200 * NB];
__device__ unsigned g_barCnt;
__device__ unsigned g_barGen;

// ---------------- packed f32x2 helpers (Blackwell FFMA2) ----------------
__device__ __forceinline__ void ffma2(unsigned long long& acc,
                                      unsigned long long a, unsigned long long b) {
    asm("fma.rn.f32x2 %0, %1, %2, %0;" : "+l"(acc) : "l"(a), "l"(b));
}
__device__ __forceinline__ unsigned long long dup2(float x) {
    unsigned long long d;
    asm("mov.b64 %0, {%1, %1};" : "=l"(d) : "r"(__float_as_uint(x)));
    return d;
}
__device__ __forceinline__ float2 unpk(unsigned long long v) {
    float2 r;
    asm("mov.b64 {%0, %1}, %2;" : "=f"(r.x), "=f"(r.y) : "l"(v));
    return r;
}

__device__ __forceinline__ float sigf(float x) { return 1.f / (1.f + __expf(-x)); }
__device__ __forceinline__ float tanhfast(float x) {
    float e = __expf(-2.f * x);
    return (1.f - e) * (1.f / (1.f + e));
}

// Sense-reversal grid barrier; requires all RCTAS CTAs co-resident.
__device__ __forceinline__ void grid_barrier() {
    __threadfence();
    __syncthreads();
    if (threadIdx.x == 0) {
        unsigned gen = atomicAdd(&g_barGen, 0u);
        unsigned a = atomicAdd(&g_barCnt, 1u);
        if (a == RCTAS - 1u) {
            atomicExch(&g_barCnt, 0u);
            __threadfence();
            atomicAdd(&g_barGen, 1u);
        } else {
            volatile unsigned* vg = &g_barGen;
            while (*vg == gen) { __nanosleep(64); }
        }
        __threadfence();
    }
    __syncthreads();
}

// ---------------- embedding: g_x[t][e][b] = emb[tokens[t][b]][e] ----------------
__global__ void k_embed(const int* __restrict__ tokens, const float* __restrict__ emb) {
    int t = blockIdx.x;
    __shared__ int stok[NB];
    if (threadIdx.x < NB) stok[threadIdx.x] = tokens[t * NB + threadIdx.x];
    __syncthreads();
    float* xo = g_x + (size_t)t * EE * NB;
    for (int lin = threadIdx.x; lin < EE * NB; lin += blockDim.x) {
        int e = lin >> 7, b = lin & 127;
        xo[lin] = __ldg(&emb[(size_t)stok[b] * EE + e]);
    }
}

// ---------------- pre GEMM: C[t][m][b] = sum_k W[m][k] * X[t][k][b] + bias1[m]+bias2[m]
// tile 128(m) x 128(b) x BK=8, 256 threads, micro 8x8 via f32x2
__global__ __launch_bounds__(256) void k_gemm_wx(
    const float* __restrict__ W,
    const float* __restrict__ bias1, const float* __restrict__ bias2,
    int xsel, int csel, int M, int K)
{
    const float* X = xsel ? g_h0 : g_x;
    float* C = csel ? g_pre_b : g_pre_f;
    __shared__ __align__(16) float As[8][128];   // [k][m]
    __shared__ __align__(16) float Bs[8][128];   // [k][b]
    const int tid = threadIdx.x;
    const int m0 = blockIdx.x * 128;
    const float* Xb = X + (size_t)blockIdx.y * K * NB;
    float* Cb = C + (size_t)blockIdx.y * M * NB;

    const int la_m = tid >> 1;            // 0..127
    const int la_k = (tid & 1) * 4;       // 0 or 4
    const int lb_k = tid >> 5;            // 0..7
    const int lb_b = (tid & 31) * 4;
    const int tm = (tid >> 4) * 8;        // row group
    const int tn = (tid & 15) * 8;        // col group

    unsigned long long acc[8][4];
#pragma unroll
    for (int i = 0; i < 8; i++)
#pragma unroll
        for (int j = 0; j < 4; j++) acc[i][j] = 0ull;

    for (int k0 = 0; k0 < K; k0 += 8) {
        float4 av = make_float4(0.f, 0.f, 0.f, 0.f);
        if (m0 + la_m < M)
            av = *(const float4*)&W[(size_t)(m0 + la_m) * K + k0 + la_k];
        float4 bv = *(const float4*)&Xb[(size_t)(k0 + lb_k) * NB + lb_b];
        __syncthreads();
        As[la_k][la_m] = av.x;
        As[la_k + 1][la_m] = av.y;
        As[la_k + 2][la_m] = av.z;
        As[la_k + 3][la_m] = av.w;
        *(float4*)&Bs[lb_k][lb_b] = bv;
        __syncthreads();
#pragma unroll
        for (int kk = 0; kk < 8; kk++) {
            float4 a0 = *(float4*)&As[kk][tm];
            float4 a1 = *(float4*)&As[kk][tm + 4];
            ulonglong2 b0 = *(ulonglong2*)&Bs[kk][tn];
            ulonglong2 b1 = *(ulonglong2*)&Bs[kk][tn + 4];
            unsigned long long ad[8];
            ad[0] = dup2(a0.x); ad[1] = dup2(a0.y); ad[2] = dup2(a0.z); ad[3] = dup2(a0.w);
            ad[4] = dup2(a1.x); ad[5] = dup2(a1.y); ad[6] = dup2(a1.z); ad[7] = dup2(a1.w);
#pragma unroll
            for (int i = 0; i < 8; i++) {
                ffma2(acc[i][0], ad[i], b0.x);
                ffma2(acc[i][1], ad[i], b0.y);
                ffma2(acc[i][2], ad[i], b1.x);
                ffma2(acc[i][3], ad[i], b1.y);
            }
        }
    }
#pragma unroll
    for (int r = 0; r < 8; r++) {
        int m = m0 + tm + r;
        if (m < M) {
            float bs = __ldg(&bias1[m]) + __ldg(&bias2[m]);
            float2 p0 = unpk(acc[r][0]), p1 = unpk(acc[r][1]);
            float2 p2 = unpk(acc[r][2]), p3 = unpk(acc[r][3]);
            float4 o0 = make_float4(p0.x + bs, p0.y + bs, p1.x + bs, p1.y + bs);
            float4 o1 = make_float4(p2.x + bs, p2.y + bs, p3.x + bs, p3.y + bs);
            *(float4*)&Cb[(size_t)m * NB + tn] = o0;
            *(float4*)&Cb[(size_t)m * NB + tn + 4] = o1;
        }
    }
}

// ---------------- persistent BiLSTM layer: 100 CTAs (50/dir, 4 units each), 128 thr
// Thread (ty = unit-in-CTA, bx = 4 batch cols) owns all 4 gates of its unit:
// gates + c state fully register-resident; W pre-duplicated for f32x2.
__global__ __launch_bounds__(128) void k_recur(
    const float* __restrict__ whh_f, const float* __restrict__ whh_b, int layer)
{
    __shared__ __align__(16) float2 Wtp[200][16];      // [k][u*4+g], value duplicated
    __shared__ __align__(16) float Hs[2][KC][NB];

    const int tid = threadIdx.x;
    const int dir = blockIdx.x / 50;
    const int ub = (blockIdx.x % 50) * 4;
    const float* whh = dir ? whh_b : whh_f;
    const float* pre = dir ? g_pre_b : g_pre_f;
    float* hb0 = g_hbuf0 + dir * 200 * NB;
    float* hb1 = g_hbuf1 + dir * 200 * NB;

    for (int idx = tid; idx < 3200; idx += 128) {
        int r = idx & 15, k = idx >> 4;
        int u = r >> 2, g = r & 3;
        float w = whh[(size_t)(g * 200 + ub + u) * 200 + k];
        Wtp[k][r] = make_float2(w, w);
    }

    const int ty = tid >> 5;        // unit in CTA (0..3)
    const int bx = (tid & 31) * 4;  // batch cols bx..bx+3

    float cc[4] = {0.f, 0.f, 0.f, 0.f};
    *(float4*)&hb0[(ub + ty) * NB + bx] = make_float4(0.f, 0.f, 0.f, 0.f);
    grid_barrier();

    for (int s = 0; s < TT; s++) {
        const int t = dir ? (TT - 1 - s) : s;
        const float* hprev = (s & 1) ? hb1 : hb0;
        float* hnext = (s & 1) ? hb0 : hb1;
        const float* pt = pre + (size_t)t * H4G * NB;

        // pre-activations for this thread's 4 gates x 4 cols (issued early)
        float4 pv[4];
#pragma unroll
        for (int g = 0; g < 4; g++)
            pv[g] = *(const float4*)&pt[(size_t)(g * 200 + ub + ty) * NB + bx];

        unsigned long long acc[4][2];
#pragma unroll
        for (int g = 0; g < 4; g++) { acc[g][0] = 0ull; acc[g][1] = 0ull; }

        // stage chunk 0 of hprev (L2 reads: L1 stale across grid barrier)
        float4 pr[5];
#pragma unroll
        for (int i = 0; i < 5; i++) {
            int idx = tid + i * 128;
            pr[i] = __ldcg((const float4*)&hprev[(idx >> 5) * NB + (idx & 31) * 4]);
        }
#pragma unroll
        for (int i = 0; i < 5; i++) {
            int idx = tid + i * 128;
            *(float4*)&Hs[0][idx >> 5][(idx & 31) * 4] = pr[i];
        }
        __syncthreads();

        for (int kc = 0; kc < 10; kc++) {
            const int cur = kc & 1;
            if (kc < 9) {
#pragma unroll
                for (int i = 0; i < 5; i++) {
                    int idx = tid + i * 128;
                    pr[i] = __ldcg((const float4*)&hprev[((kc + 1) * KC + (idx >> 5)) * NB + (idx & 31) * 4]);
                }
            }
#pragma unroll 5
            for (int kk = 0; kk < KC; kk++) {
                ulonglong2 w01 = *(const ulonglong2*)&Wtp[kc * KC + kk][ty * 4];
                ulonglong2 w23 = *(const ulonglong2*)&Wtp[kc * KC + kk][ty * 4 + 2];
                ulonglong2 h = *(const ulonglong2*)&Hs[cur][kk][bx];
                ffma2(acc[0][0], w01.x, h.x); ffma2(acc[0][1], w01.x, h.y);
                ffma2(acc[1][0], w01.y, h.x); ffma2(acc[1][1], w01.y, h.y);
                ffma2(acc[2][0], w23.x, h.x); ffma2(acc[2][1], w23.x, h.y);
                ffma2(acc[3][0], w23.y, h.x); ffma2(acc[3][1], w23.y, h.y);
            }
            if (kc < 9) {
#pragma unroll
                for (int i = 0; i < 5; i++) {
                    int idx = tid + i * 128;
                    *(float4*)&Hs[cur ^ 1][idx >> 5][(idx & 31) * 4] = pr[i];
                }
            }
            __syncthreads();
        }

        // gates fully in registers: g index 0=i,1=f,2=g,3=o
        float gv[4][4];
#pragma unroll
        for (int g = 0; g < 4; g++) {
            float2 a0 = unpk(acc[g][0]);
            float2 a1 = unpk(acc[g][1]);
            gv[g][0] = a0.x + pv[g].x;
            gv[g][1] = a0.y + pv[g].y;
            gv[g][2] = a1.x + pv[g].z;
            gv[g][3] = a1.y + pv[g].w;
        }
        float hv[4];
#pragma unroll
        for (int j = 0; j < 4; j++) {
            float iv = sigf(gv[0][j]);
            float fv = sigf(gv[1][j]);
            float gg = tanhfast(gv[2][j]);
            float ov = sigf(gv[3][j]);
            float c = fv * cc[j] + iv * gg;
            cc[j] = c;
            hv[j] = ov * tanhfast(c);
        }
        *(float4*)&hnext[(ub + ty) * NB + bx] = make_float4(hv[0], hv[1], hv[2], hv[3]);
        if (layer == 0) {
            *(float4*)&g_h0[((size_t)t * 400 + dir * 200 + ub + ty) * NB + bx] =
                make_float4(hv[0], hv[1], hv[2], hv[3]);
        } else {
#pragma unroll
            for (int j = 0; j < 4; j++)
                g_hbt[((size_t)(bx + j) * TT + t) * 400 + dir * 200 + ub + ty] = hv[j];
        }
        grid_barrier();
    }
}

// ---------------- fused path-gather + MLP1 (tanh): tile 128 samples x 64 units, K=800
__global__ __launch_bounds__(256) void k_gather_mlp1(
    const int* __restrict__ paths, const float* __restrict__ w1, const float* __restrict__ b1)
{
    __shared__ __align__(16) float As[8][128];
    __shared__ __align__(16) float Bs[8][64];
    __shared__ long long abase[128][2];
    const int tid = threadIdx.x;
    const int s0 = blockIdx.x * 128;
    const int n0 = blockIdx.y * 64;

    {
        int i = tid >> 1, j = tid & 1;
        int s = s0 + i;
        int tval = paths[(size_t)s * 2 + j];
        int b = s >> 8;
        abase[i][j] = (tval >= 0) ? ((long long)b * TT + tval) * 400LL : -1LL;
    }
    __syncthreads();

    const int la_i = tid >> 1;            // sample 0..127
    const int la_k = (tid & 1) * 4;       // k offset 0/4
    const int lb_n = tid >> 2;            // 0..63
    const int lb_k = (tid & 3) * 2;
    const int tm = (tid >> 4) * 8;        // sample rows
    const int tn = (tid & 15) * 4;        // n cols

    unsigned long long acc[8][2];
#pragma unroll
    for (int i = 0; i < 8; i++) { acc[i][0] = 0ull; acc[i][1] = 0ull; }

    for (int k0 = 0; k0 < 800; k0 += 8) {
        int k = k0 + la_k;
        int j = (k >= 400) ? 1 : 0;
        int u = k - j * 400;
        long long base = abase[la_i][j];
        float4 av = make_float4(0.f, 0.f, 0.f, 0.f);
        if (base >= 0) av = *(const float4*)&g_hbt[base + u];
        float2 bv = make_float2(0.f, 0.f);
        int n = n0 + lb_n;
        if (n < 200) bv = *(const float2*)&w1[(size_t)n * 800 + k0 + lb_k];
        __syncthreads();
        As[la_k][la_i] = av.x;
        As[la_k + 1][la_i] = av.y;
        As[la_k + 2][la_i] = av.z;
        As[la_k + 3][la_i] = av.w;
        Bs[lb_k][lb_n] = bv.x;
        Bs[lb_k + 1][lb_n] = bv.y;
        __syncthreads();
#pragma unroll
        for (int kk = 0; kk < 8; kk++) {
            float4 a0 = *(float4*)&As[kk][tm];
            float4 a1 = *(float4*)&As[kk][tm + 4];
            ulonglong2 b2v = *(ulonglong2*)&Bs[kk][tn];
            unsigned long long ad[8];
            ad[0] = dup2(a0.x); ad[1] = dup2(a0.y); ad[2] = dup2(a0.z); ad[3] = dup2(a0.w);
            ad[4] = dup2(a1.x); ad[5] = dup2(a1.y); ad[6] = dup2(a1.z); ad[7] = dup2(a1.w);
#pragma unroll
            for (int i = 0; i < 8; i++) {
                ffma2(acc[i][0], ad[i], b2v.x);
                ffma2(acc[i][1], ad[i], b2v.y);
            }
        }
    }
#pragma unroll
    for (int r = 0; r < 8; r++) {
        int s = s0 + tm + r;
        float2 p0 = unpk(acc[r][0]), p1 = unpk(acc[r][1]);
        float o[4] = {p0.x, p0.y, p1.x, p1.y};
        float4 ov;
        float* po = &ov.x;
#pragma unroll
        for (int c2 = 0; c2 < 4; c2++) {
            int n = n0 + tn + c2;
            po[c2] = (n < 200) ? tanhf(o[c2] + __ldg(&b1[n])) : 0.f;
        }
        if (n0 + tn < 200)
            *(float4*)&g_hid[(size_t)s * 200 + n0 + tn] = ov;
    }
}

// ---------------- MLP2 + softmax: one warp per sample ----------------
__global__ __launch_bounds__(128) void k_mlp2(
    const float* __restrict__ w2, const float* __restrict__ b2, float* __restrict__ out)
{
    __shared__ float w2s[800];
    __shared__ float b2s[4];
    const int tid = threadIdx.x;
    for (int i = tid; i < 800; i += 128) w2s[i] = w2[i];
    if (tid < 4) b2s[tid] = b2[tid];
    __syncthreads();
    const int warp = tid >> 5, lane = tid & 31;
    const int s = blockIdx.x * 4 + warp;
    const float* hr = g_hid + (size_t)s * 200;
    float a0 = 0.f, a1 = 0.f, a2 = 0.f, a3 = 0.f;
    for (int k = lane; k < 200; k += 32) {
        float h = hr[k];
        a0 += h * w2s[k];
        a1 += h * w2s[200 + k];
        a2 += h * w2s[400 + k];
        a3 += h * w2s[600 + k];
    }
#pragma unroll
    for (int o = 16; o > 0; o >>= 1) {
        a0 += __shfl_down_sync(0xffffffffu, a0, o);
        a1 += __shfl_down_sync(0xffffffffu, a1, o);
        a2 += __shfl_down_sync(0xffffffffu, a2, o);
        a3 += __shfl_down_sync(0xffffffffu, a3, o);
    }
    if (lane == 0) {
        float l0 = a0 + b2s[0], l1 = a1 + b2s[1], l2 = a2 + b2s[2], l3 = a3 + b2s[3];
        float m = fmaxf(fmaxf(l0, l1), fmaxf(l2, l3));
        float e0 = expf(l0 - m), e1 = expf(l1 - m), e2 = expf(l2 - m), e3 = expf(l3 - m);
        float inv = 1.f / (e0 + e1 + e2 + e3);
        float4 r = make_float4(e0 * inv, e1 * inv, e2 * inv, e3 * inv);
        *(float4*)&out[(size_t)s * 4] = r;
    }
}

extern "C" void kernel_launch(void* const* d_in, const int* in_sizes, int n_in,
                              void* d_out, int out_size)
{
    const int* tokens = (const int*)d_in[0];
    const int* paths = (const int*)d_in[1];
    const float* emb = (const float*)d_in[2];
    const float* wih0f = (const float*)d_in[3];
    const float* whh0f = (const float*)d_in[4];
    const float* bih0f = (const float*)d_in[5];
    const float* bhh0f = (const float*)d_in[6];
    const float* wih0b = (const float*)d_in[7];
    const float* whh0b = (const float*)d_in[8];
    const float* bih0b = (const float*)d_in[9];
    const float* bhh0b = (const float*)d_in[10];
    const float* wih1f = (const float*)d_in[11];
    const float* whh1f = (const float*)d_in[12];
    const float* bih1f = (const float*)d_in[13];
    const float* bhh1f = (const float*)d_in[14];
    const float* wih1b = (const float*)d_in[15];
    const float* whh1b = (const float*)d_in[16];
    const float* bih1b = (const float*)d_in[17];
    const float* bhh1b = (const float*)d_in[18];
    const float* w1 = (const float*)d_in[19];
    const float* b1 = (const float*)d_in[20];
    const float* w2 = (const float*)d_in[21];
    const float* b2 = (const float*)d_in[22];
    float* out = (float*)d_out;

    k_embed<<<TT, 256>>>(tokens, emb);

    dim3 gp(7, TT);
    k_gemm_wx<<<gp, 256>>>(wih0f, bih0f, bhh0f, 0, 0, 800, 200);
    k_gemm_wx<<<gp, 256>>>(wih0b, bih0b, bhh0b, 0, 1, 800, 200);
    k_recur<<<RCTAS, 128>>>(whh0f, whh0b, 0);

    k_gemm_wx<<<gp, 256>>>(wih1f, bih1f, bhh1f, 1, 0, 800, 400);
    k_gemm_wx<<<gp, 256>>>(wih1b, bih1b, bhh1b, 1, 1, 800, 400);
    k_recur<<<RCTAS, 128>>>(whh1f, whh1b, 1);

    dim3 g4(NSAMP / 128, 4);
    k_gather_mlp1<<<g4, 256>>>(paths, w1, b1);
    k_mlp2<<<NSAMP / 4, 128>>>(w2, b2, out);
}

// round 6
// speedup vs baseline: 1.1264x; 1.0923x over previous
#include <cuda_runtime.h>
#include <cuda_bf16.h>
#include <cstdint>

#define TT 512
#define NB 128
#define NSAMP 32768
#define RCTAS 100
#define KC 20
#define KP0 224
#define KP1 416
#define AP 40   // padded smem stride (bf16 elems) for 32-wide k chunks

// ---------------- static scratch (no allocation) ----------------
__device__ float g_pre_f[(size_t)TT * 800 * NB];   // (t, gate, b)
__device__ float g_pre_b[(size_t)TT * 800 * NB];
__device__ float g_h0[(size_t)TT * 400 * NB];      // layer0 out (t, u, b)
__device__ float g_hbt[(size_t)NB * TT * 400];     // layer1 out (b, t, u)
__device__ float g_hid[(size_t)NSAMP * 200];       // MLP hidden (s, n)
__device__ float g_hbuf0[2 * 200 * NB];            // h ping-pong [dir][u][b]
__device__ float g_hbuf1[2 * 200 * NB];
__device__ unsigned g_barCnt;
__device__ unsigned g_barGen;

// bf16-split operand buffers (hi + lo) for tensor-core GEMMs
__device__ __align__(16) __nv_bfloat16 g_w0h[(size_t)2 * 896 * KP0];  // [dir][m][k]
__device__ __align__(16) __nv_bfloat16 g_w0l[(size_t)2 * 896 * KP0];
__device__ __align__(16) __nv_bfloat16 g_w1h[(size_t)2 * 896 * KP1];
__device__ __align__(16) __nv_bfloat16 g_w1l[(size_t)2 * 896 * KP1];
__device__ __align__(16) __nv_bfloat16 g_xh[(size_t)TT * NB * KP0];   // (t, b, k)
__device__ __align__(16) __nv_bfloat16 g_xl[(size_t)TT * NB * KP0];
__device__ __align__(16) __nv_bfloat16 g_h0h[(size_t)TT * NB * KP1];  // (t, b, k)
__device__ __align__(16) __nv_bfloat16 g_h0l[(size_t)TT * NB * KP1];

// ---------------- helpers ----------------
__device__ __forceinline__ void ffma2(unsigned long long& acc,
                                      unsigned long long a, unsigned long long b) {
    asm("fma.rn.f32x2 %0, %1, %2, %0;" : "+l"(acc) : "l"(a), "l"(b));
}
__device__ __forceinline__ float2 unpk(unsigned long long v) {
    float2 r;
    asm("mov.b64 {%0, %1}, %2;" : "=f"(r.x), "=f"(r.y) : "l"(v));
    return r;
}
__device__ __forceinline__ float sigf(float x) { return 1.f / (1.f + __expf(-x)); }
__device__ __forceinline__ float tanhfast(float x) {
    float e = __expf(-2.f * x);
    return (1.f - e) * (1.f / (1.f + e));
}
__device__ __forceinline__ void bfsplit(float v, __nv_bfloat16& h, __nv_bfloat16& l) {
    h = __float2bfloat16(v);
    l = __float2bfloat16(v - __bfloat162float(h));
}
__device__ __forceinline__ uint32_t smem_u32(const void* p) {
    uint32_t a;
    asm("{ .reg .u64 t; cvta.to.shared.u64 t, %1; cvt.u32.u64 %0, t; }" : "=r"(a) : "l"(p));
    return a;
}

__device__ __forceinline__ void ldsm_x4(uint32_t addr, uint32_t r[4]) {
    asm volatile("ldmatrix.sync.aligned.m8n8.x4.shared.b16 {%0,%1,%2,%3}, [%4];"
        : "=r"(r[0]), "=r"(r[1]), "=r"(r[2]), "=r"(r[3]) : "r"(addr));
}
__device__ __forceinline__ void mma16816(float d[4], const uint32_t a[4],
                                         uint32_t b0, uint32_t b1) {
    asm volatile(
        "mma.sync.aligned.m16n8k16.row.col.f32.bf16.bf16.f32 "
        "{%0,%1,%2,%3}, {%4,%5,%6,%7}, {%8,%9}, {%0,%1,%2,%3};"
        : "+f"(d[0]), "+f"(d[1]), "+f"(d[2]), "+f"(d[3])
        : "r"(a[0]), "r"(a[1]), "r"(a[2]), "r"(a[3]), "r"(b0), "r"(b1));
}

// Sense-reversal grid barrier; requires all RCTAS CTAs co-resident.
__device__ __forceinline__ void grid_barrier() {
    __threadfence();
    __syncthreads();
    if (threadIdx.x == 0) {
        unsigned gen = atomicAdd(&g_barGen, 0u);
        unsigned a = atomicAdd(&g_barCnt, 1u);
        if (a == RCTAS - 1u) {
            atomicExch(&g_barCnt, 0u);
            __threadfence();
            atomicAdd(&g_barGen, 1u);
        } else {
            volatile unsigned* vg = &g_barGen;
            while (*vg == gen) { __nanosleep(64); }
        }
        __threadfence();
    }
    __syncthreads();
}

// ---------------- embedding -> bf16 hi/lo, (t, b, k) padded to KP0 ----------------
__global__ __launch_bounds__(256) void k_embsplit(const int* __restrict__ tokens,
                                                  const float* __restrict__ emb) {
    int t = blockIdx.x;
    __shared__ int stok[NB];
    if (threadIdx.x < NB) stok[threadIdx.x] = tokens[t * NB + threadIdx.x];
    __syncthreads();
    size_t base = (size_t)t * NB * KP0;
    for (int idx = threadIdx.x; idx < NB * KP0; idx += 256) {
        int b = idx / KP0, k = idx - b * KP0;
        float v = (k < 200) ? __ldg(&emb[(size_t)stok[b] * 200 + k]) : 0.f;
        __nv_bfloat16 h, l;
        bfsplit(v, h, l);
        g_xh[base + idx] = h;
        g_xl[base + idx] = l;
    }
}

// ---------------- W -> bf16 hi/lo, padded rows 896 / k KPv ----------------
__global__ __launch_bounds__(256) void k_wsplit(const float* __restrict__ w,
                                                int layer, int dir, int K, int KPv) {
    __nv_bfloat16* dh = (layer ? g_w1h : g_w0h) + (size_t)dir * 896 * KPv;
    __nv_bfloat16* dl = (layer ? g_w1l : g_w0l) + (size_t)dir * 896 * KPv;
    int idx = blockIdx.x * 256 + threadIdx.x;
    if (idx >= 896 * KPv) return;
    int m = idx / KPv, k = idx - m * KPv;
    float v = (m < 800 && k < K) ? __ldg(&w[(size_t)m * K + k]) : 0.f;
    __nv_bfloat16 h, l;
    bfsplit(v, h, l);
    dh[idx] = h;
    dl[idx] = l;
}

// ---------------- layer0 h (t,u,b) -> bf16 hi/lo (t,b,k) padded KP1 ----------------
__global__ __launch_bounds__(256) void k_h0split() {
    int t = blockIdx.x;
    __shared__ float ts[32][NB + 1];
    for (int c = 0; c < KP1 / 32; c++) {
        int u0 = c * 32;
        __syncthreads();
        for (int i = threadIdx.x; i < 32 * NB; i += 256) {
            int u = i >> 7, b = i & 127;
            ts[u][b] = (u0 + u < 400) ? g_h0[((size_t)t * 400 + u0 + u) * NB + b] : 0.f;
        }
        __syncthreads();
        for (int i = threadIdx.x; i < NB * 32; i += 256) {
            int b = i >> 5, u = i & 31;
            float v = ts[u][b];
            __nv_bfloat16 h, l;
            bfsplit(v, h, l);
            size_t o = ((size_t)t * NB + b) * KP1 + u0 + u;
            g_h0h[o] = h;
            g_h0l[o] = l;
        }
    }
}

// ---------------- tensor-core pre-GEMM (mma.sync bf16 hi/lo split) ----------------
// D[m(128), b(128)] = sum_k W[m0+m][k] * X[t][b][k] + bias1[m] + bias2[m]
// grid (7 m-tiles, TT, 2 dirs), 256 thr = 8 warps (4m x 2n), warp tile 32x64.
// B is stored [n][k] row-major => NON-trans ldmatrix yields the col-major B fragment.
__global__ __launch_bounds__(256) void k_gemm_mma(
    int layer,
    const float* __restrict__ bih_f, const float* __restrict__ bhh_f,
    const float* __restrict__ bih_b, const float* __restrict__ bhh_b)
{
    __shared__ __align__(16) __nv_bfloat16 sAh[128 * AP], sAl[128 * AP];
    __shared__ __align__(16) __nv_bfloat16 sBh[128 * AP], sBl[128 * AP];

    const int tid = threadIdx.x;
    const int warp = tid >> 5, lane = tid & 31;
    const int m0 = blockIdx.x * 128;
    const int t = blockIdx.y;
    const int dir = blockIdx.z;
    const int KPv = layer ? KP1 : KP0;
    const int nchunk = KPv >> 5;
    const __nv_bfloat16* Ah = (layer ? g_w1h : g_w0h) + (size_t)dir * 896 * KPv + (size_t)m0 * KPv;
    const __nv_bfloat16* Al = (layer ? g_w1l : g_w0l) + (size_t)dir * 896 * KPv + (size_t)m0 * KPv;
    const __nv_bfloat16* Bh = (layer ? g_h0h : g_xh) + (size_t)t * NB * KPv;
    const __nv_bfloat16* Bl = (layer ? g_h0l : g_xl) + (size_t)t * NB * KPv;

    const int wm = (warp & 3) * 32;
    const int wn = (warp >> 2) * 64;
    const int lrow = lane & 15;
    const int lcol = (lane >> 4) * 8;

    const uint32_t aAh = smem_u32(sAh), aAl = smem_u32(sAl);
    const uint32_t aBh = smem_u32(sBh), aBl = smem_u32(sBl);

    float acc[2][8][4];
#pragma unroll
    for (int i = 0; i < 2; i++)
#pragma unroll
        for (int n = 0; n < 8; n++)
#pragma unroll
            for (int q = 0; q < 4; q++) acc[i][n][q] = 0.f;

    const int srow = tid >> 2;            // staging: row 0..63 (x2 iters -> 128)
    const int skv = (tid & 3) * 8;        // k element offset

    for (int c = 0; c < nchunk; c++) {
        const int kb0 = c * 32;
#pragma unroll
        for (int jv = 0; jv < 2; jv++) {
            int row = srow + jv * 64;
            size_t go = (size_t)row * KPv + kb0 + skv;
            int so = row * AP + skv;
            *(uint4*)&sAh[so] = *(const uint4*)(Ah + go);
            *(uint4*)&sAl[so] = *(const uint4*)(Al + go);
            *(uint4*)&sBh[so] = *(const uint4*)(Bh + go);
            *(uint4*)&sBl[so] = *(const uint4*)(Bl + go);
        }
        __syncthreads();
#pragma unroll
        for (int ks = 0; ks < 2; ks++) {
            const int kb = ks * 16;
            uint32_t ah[2][4], al[2][4];
#pragma unroll
            for (int i = 0; i < 2; i++) {
                uint32_t off = (uint32_t)(((wm + i * 16 + lrow) * AP + kb + lcol) * 2);
                ldsm_x4(aAh + off, ah[i]);
                ldsm_x4(aAl + off, al[i]);
            }
#pragma unroll
            for (int p = 0; p < 4; p++) {
                uint32_t off = (uint32_t)(((wn + p * 16 + lrow) * AP + kb + lcol) * 2);
                uint32_t bh[4], bl[4];
                ldsm_x4(aBh + off, bh);   // NON-trans: B stored [n][k]
                ldsm_x4(aBl + off, bl);
#pragma unroll
                for (int i = 0; i < 2; i++) {
                    mma16816(acc[i][2 * p],     ah[i], bh[0], bh[2]);
                    mma16816(acc[i][2 * p + 1], ah[i], bh[1], bh[3]);
                    mma16816(acc[i][2 * p],     ah[i], bl[0], bl[2]);
                    mma16816(acc[i][2 * p + 1], ah[i], bl[1], bl[3]);
                    mma16816(acc[i][2 * p],     al[i], bh[0], bh[2]);
                    mma16816(acc[i][2 * p + 1], al[i], bh[1], bh[3]);
                }
            }
        }
        __syncthreads();
    }

    // epilogue: bias + store fp32 (t, gate, b)
    const float* b1 = dir ? bih_b : bih_f;
    const float* b2 = dir ? bhh_b : bhh_f;
    float* outp = (dir ? g_pre_b : g_pre_f) + ((size_t)t * 800 + m0) * NB;
#pragma unroll
    for (int i = 0; i < 2; i++) {
#pragma unroll
        for (int half = 0; half < 2; half++) {
            int ml = wm + i * 16 + half * 8 + (lane >> 2);
            if (m0 + ml < 800) {
                float bs = __ldg(&b1[m0 + ml]) + __ldg(&b2[m0 + ml]);
                float* op = outp + (size_t)ml * NB + wn + (lane & 3) * 2;
#pragma unroll
                for (int n = 0; n < 8; n++) {
                    float2 v = make_float2(acc[i][n][half * 2] + bs,
                                           acc[i][n][half * 2 + 1] + bs);
                    *(float2*)(op + n * 8) = v;
                }
            }
        }
    }
}

// ---------------- persistent BiLSTM layer: 100 CTAs x 256 threads ----------------
// thread = (ty = unit-in-CTA 0..3, bx = 2 batch cols); gates + c state in registers.
__global__ __launch_bounds__(256) void k_recur(
    const float* __restrict__ whh_f, const float* __restrict__ whh_b, int layer)
{
    __shared__ __align__(16) float2 Wtp[200][16];  // [k][u*4+g], duplicated for f32x2
    __shared__ __align__(16) float Hs[2][KC][NB];

    const int tid = threadIdx.x;
    const int dir = blockIdx.x / 50;
    const int ub = (blockIdx.x % 50) * 4;
    const float* whh = dir ? whh_b : whh_f;
    const float* pre = dir ? g_pre_b : g_pre_f;
    float* hb0 = g_hbuf0 + dir * 200 * NB;
    float* hb1 = g_hbuf1 + dir * 200 * NB;

    for (int idx = tid; idx < 3200; idx += 256) {
        int r = idx & 15, k = idx >> 4;
        int u = r >> 2, g = r & 3;
        float w = whh[(size_t)(g * 200 + ub + u) * 200 + k];
        Wtp[k][r] = make_float2(w, w);
    }

    const int ty = tid >> 6;        // unit in CTA (0..3)
    const int bx = (tid & 63) * 2;  // batch cols bx, bx+1

    float cc[2] = {0.f, 0.f};
    *(float2*)&hb0[(ub + ty) * NB + bx] = make_float2(0.f, 0.f);
    grid_barrier();

    for (int s = 0; s < TT; s++) {
        const int t = dir ? (TT - 1 - s) : s;
        const float* hprev = (s & 1) ? hb1 : hb0;
        float* hnext = (s & 1) ? hb0 : hb1;
        const float* pt = pre + (size_t)t * 800 * NB;

        float2 pv[4];
#pragma unroll
        for (int g = 0; g < 4; g++)
            pv[g] = *(const float2*)&pt[(size_t)(g * 200 + ub + ty) * NB + bx];

        unsigned long long acc[4] = {0ull, 0ull, 0ull, 0ull};

        float4 pr[5];
        if (tid < 128) {
#pragma unroll
            for (int i = 0; i < 5; i++) {
                int idx = tid + i * 128;
                pr[i] = __ldcg((const float4*)&hprev[(idx >> 5) * NB + (idx & 31) * 4]);
            }
#pragma unroll
            for (int i = 0; i < 5; i++) {
                int idx = tid + i * 128;
                *(float4*)&Hs[0][idx >> 5][(idx & 31) * 4] = pr[i];
            }
        }
        __syncthreads();

        for (int kc = 0; kc < 10; kc++) {
            const int cur = kc & 1;
            if (tid < 128 && kc < 9) {
#pragma unroll
                for (int i = 0; i < 5; i++) {
                    int idx = tid + i * 128;
                    pr[i] = __ldcg((const float4*)&hprev[((kc + 1) * KC + (idx >> 5)) * NB + (idx & 31) * 4]);
                }
            }
#pragma unroll 5
            for (int kk = 0; kk < KC; kk++) {
                ulonglong2 w01 = *(const ulonglong2*)&Wtp[kc * KC + kk][ty * 4];
                ulonglong2 w23 = *(const ulonglong2*)&Wtp[kc * KC + kk][ty * 4 + 2];
                unsigned long long h = *(const unsigned long long*)&Hs[cur][kk][bx];
                ffma2(acc[0], w01.x, h);
                ffma2(acc[1], w01.y, h);
                ffma2(acc[2], w23.x, h);
                ffma2(acc[3], w23.y, h);
            }
            if (tid < 128 && kc < 9) {
#pragma unroll
                for (int i = 0; i < 5; i++) {
                    int idx = tid + i * 128;
                    *(float4*)&Hs[cur ^ 1][idx >> 5][(idx & 31) * 4] = pr[i];
                }
            }
            __syncthreads();
        }

        float gv[4][2];
#pragma unroll
        for (int g = 0; g < 4; g++) {
            float2 a = unpk(acc[g]);
            gv[g][0] = a.x + pv[g].x;
            gv[g][1] = a.y + pv[g].y;
        }
        float hv[2];
#pragma unroll
        for (int j = 0; j < 2; j++) {
            float iv = sigf(gv[0][j]);
            float fv = sigf(gv[1][j]);
            float gg = tanhfast(gv[2][j]);
            float ov = sigf(gv[3][j]);
            float c = fv * cc[j] + iv * gg;
            cc[j] = c;
            hv[j] = ov * tanhfast(c);
        }
        *(float2*)&hnext[(ub + ty) * NB + bx] = make_float2(hv[0], hv[1]);
        if (layer == 0) {
            *(float2*)&g_h0[((size_t)t * 400 + dir * 200 + ub + ty) * NB + bx] =
                make_float2(hv[0], hv[1]);
        } else {
#pragma unroll
            for (int j = 0; j < 2; j++)
                g_hbt[((size_t)(bx + j) * TT + t) * 400 + dir * 200 + ub + ty] = hv[j];
        }
        grid_barrier();
    }
}

// ---------------- fused path-gather + MLP1 (tanh) ----------------
__global__ __launch_bounds__(256) void k_gather_mlp1(
    const int* __restrict__ paths, const float* __restrict__ w1, const float* __restrict__ b1)
{
    __shared__ __align__(16) float As[8][128];
    __shared__ __align__(16) float Bs[8][64];
    __shared__ long long abase[128][2];
    const int tid = threadIdx.x;
    const int s0 = blockIdx.x * 128;
    const int n0 = blockIdx.y * 64;

    {
        int i = tid >> 1, j = tid & 1;
        int s = s0 + i;
        int tval = paths[(size_t)s * 2 + j];
        int b = s >> 8;
        abase[i][j] = (tval >= 0) ? ((long long)b * TT + tval) * 400LL : -1LL;
    }
    __syncthreads();

    const int la_i = tid >> 1;
    const int la_k = (tid & 1) * 4;
    const int lb_n = tid >> 2;
    const int lb_k = (tid & 3) * 2;
    const int tm = (tid >> 4) * 8;
    const int tn = (tid & 15) * 4;

    float acc[8][4];
#pragma unroll
    for (int i = 0; i < 8; i++)
#pragma unroll
        for (int j = 0; j < 4; j++) acc[i][j] = 0.f;

    for (int k0 = 0; k0 < 800; k0 += 8) {
        int k = k0 + la_k;
        int j = (k >= 400) ? 1 : 0;
        int u = k - j * 400;
        long long base = abase[la_i][j];
        float4 av = make_float4(0.f, 0.f, 0.f, 0.f);
        if (base >= 0) av = *(const float4*)&g_hbt[base + u];
        float2 bv = make_float2(0.f, 0.f);
        int n = n0 + lb_n;
        if (n < 200) bv = *(const float2*)&w1[(size_t)n * 800 + k0 + lb_k];
        __syncthreads();
        As[la_k][la_i] = av.x;
        As[la_k + 1][la_i] = av.y;
        As[la_k + 2][la_i] = av.z;
        As[la_k + 3][la_i] = av.w;
        Bs[lb_k][lb_n] = bv.x;
        Bs[lb_k + 1][lb_n] = bv.y;
        __syncthreads();
#pragma unroll
        for (int kk = 0; kk < 8; kk++) {
            float4 a0 = *(float4*)&As[kk][tm];
            float4 a1 = *(float4*)&As[kk][tm + 4];
            float4 b4 = *(float4*)&Bs[kk][tn];
            float avv[8] = {a0.x, a0.y, a0.z, a0.w, a1.x, a1.y, a1.z, a1.w};
            float bvv[4] = {b4.x, b4.y, b4.z, b4.w};
#pragma unroll
            for (int i = 0; i < 8; i++)
#pragma unroll
                for (int j2 = 0; j2 < 4; j2++) acc[i][j2] += avv[i] * bvv[j2];
        }
    }
#pragma unroll
    for (int r = 0; r < 8; r++) {
        int s = s0 + tm + r;
        float4 ov;
        float* po = &ov.x;
#pragma unroll
        for (int c2 = 0; c2 < 4; c2++) {
            int n = n0 + tn + c2;
            po[c2] = (n < 200) ? tanhf(acc[r][c2] + __ldg(&b1[n])) : 0.f;
        }
        if (n0 + tn < 200)
            *(float4*)&g_hid[(size_t)s * 200 + n0 + tn] = ov;
    }
}

// ---------------- MLP2 + softmax: one warp per sample ----------------
__global__ __launch_bounds__(128) void k_mlp2(
    const float* __restrict__ w2, const float* __restrict__ b2, float* __restrict__ out)
{
    __shared__ float w2s[800];
    __shared__ float b2s[4];
    const int tid = threadIdx.x;
    for (int i = tid; i < 800; i += 128) w2s[i] = w2[i];
    if (tid < 4) b2s[tid] = b2[tid];
    __syncthreads();
    const int warp = tid >> 5, lane = tid & 31;
    const int s = blockIdx.x * 4 + warp;
    const float* hr = g_hid + (size_t)s * 200;
    float a0 = 0.f, a1 = 0.f, a2 = 0.f, a3 = 0.f;
    for (int k = lane; k < 200; k += 32) {
        float h = hr[k];
        a0 += h * w2s[k];
        a1 += h * w2s[200 + k];
        a2 += h * w2s[400 + k];
        a3 += h * w2s[600 + k];
    }
#pragma unroll
    for (int o = 16; o > 0; o >>= 1) {
        a0 += __shfl_down_sync(0xffffffffu, a0, o);
        a1 += __shfl_down_sync(0xffffffffu, a1, o);
        a2 += __shfl_down_sync(0xffffffffu, a2, o);
        a3 += __shfl_down_sync(0xffffffffu, a3, o);
    }
    if (lane == 0) {
        float l0 = a0 + b2s[0], l1 = a1 + b2s[1], l2 = a2 + b2s[2], l3 = a3 + b2s[3];
        float m = fmaxf(fmaxf(l0, l1), fmaxf(l2, l3));
        float e0 = expf(l0 - m), e1 = expf(l1 - m), e2 = expf(l2 - m), e3 = expf(l3 - m);
        float inv = 1.f / (e0 + e1 + e2 + e3);
        float4 r = make_float4(e0 * inv, e1 * inv, e2 * inv, e3 * inv);
        *(float4*)&out[(size_t)s * 4] = r;
    }
}

extern "C" void kernel_launch(void* const* d_in, const int* in_sizes, int n_in,
                              void* d_out, int out_size)
{
    const int* tokens = (const int*)d_in[0];
    const int* paths = (const int*)d_in[1];
    const float* emb = (const float*)d_in[2];
    const float* wih0f = (const float*)d_in[3];
    const float* whh0f = (const float*)d_in[4];
    const float* bih0f = (const float*)d_in[5];
    const float* bhh0f = (const float*)d_in[6];
    const float* wih0b = (const float*)d_in[7];
    const float* whh0b = (const float*)d_in[8];
    const float* bih0b = (const float*)d_in[9];
    const float* bhh0b = (const float*)d_in[10];
    const float* wih1f = (const float*)d_in[11];
    const float* whh1f = (const float*)d_in[12];
    const float* bih1f = (const float*)d_in[13];
    const float* bhh1f = (const float*)d_in[14];
    const float* wih1b = (const float*)d_in[15];
    const float* whh1b = (const float*)d_in[16];
    const float* bih1b = (const float*)d_in[17];
    const float* bhh1b = (const float*)d_in[18];
    const float* w1 = (const float*)d_in[19];
    const float* b1 = (const float*)d_in[20];
    const float* w2 = (const float*)d_in[21];
    const float* b2 = (const float*)d_in[22];
    float* out = (float*)d_out;

    // operand prep (bf16 split)
    k_embsplit<<<TT, 256>>>(tokens, emb);
    int nb0 = (896 * KP0 + 255) / 256;
    int nb1 = (896 * KP1 + 255) / 256;
    k_wsplit<<<nb0, 256>>>(wih0f, 0, 0, 200, KP0);
    k_wsplit<<<nb0, 256>>>(wih0b, 0, 1, 200, KP0);
    k_wsplit<<<nb1, 256>>>(wih1f, 1, 0, 400, KP1);
    k_wsplit<<<nb1, 256>>>(wih1b, 1, 1, 400, KP1);

    dim3 gg(7, TT, 2);
    k_gemm_mma<<<gg, 256>>>(0, bih0f, bhh0f, bih0b, bhh0b);
    k_recur<<<RCTAS, 256>>>(whh0f, whh0b, 0);
    k_h0split<<<TT, 256>>>();
    k_gemm_mma<<<gg, 256>>>(1, bih1f, bhh1f, bih1b, bhh1b);
    k_recur<<<RCTAS, 256>>>(whh1f, whh1b, 1);

    dim3 g4(NSAMP / 128, 4);
    k_gather_mlp1<<<g4, 256>>>(paths, w1, b1);
    k_mlp2<<<NSAMP / 4, 128>>>(w2, b2, out);
}